// round 5
// baseline (speedup 1.0000x reference)
#include <cuda_runtime.h>
#include <cstdint>

#define FULLMASK 0xFFFFFFFFu
typedef unsigned long long ULL;

static constexpr int L = 64;
static constexpr int H = 32;
static constexpr int B = 1024;
static constexpr float LOG2E = 1.4426950408889634f;
static constexpr float LN2   = 0.6931471805599453f;

__device__ __forceinline__ ULL pack2(float lo, float hi) {
    ULL r; asm("mov.b64 %0, {%1, %2};" : "=l"(r) : "f"(lo), "f"(hi)); return r;
}
__device__ __forceinline__ void unpack2(ULL v, float& lo, float& hi) {
    asm("mov.b64 {%0, %1}, %2;" : "=f"(lo), "=f"(hi) : "l"(v));
}
__device__ __forceinline__ ULL ffma2(ULL a, ULL b, ULL c) {
    ULL d; asm("fma.rn.f32x2 %0, %1, %2, %3;" : "=l"(d) : "l"(a), "l"(b), "l"(c)); return d;
}
__device__ __forceinline__ ULL fadd2(ULL a, ULL b) {
    ULL d; asm("add.rn.f32x2 %0, %1, %2;" : "=l"(d) : "l"(a), "l"(b)); return d;
}
__device__ __forceinline__ float ex2f(float x) {
    float r; asm("ex2.approx.f32 %0, %1;" : "=f"(r) : "f"(x)); return r;
}
// ELU(alpha=1) on a log2-scaled pre-activation p2 = pre * log2(e).
__device__ __forceinline__ float elu2(float p2) {
    return fmaxf(p2 * LN2, 0.f) + (ex2f(fminf(p2, 0.f)) - 1.f);
}

__global__ void __launch_bounds__(32)
rnn2d_kernel(const int* __restrict__ x,        // [B, L, L] in {0,1}
             const float* __restrict__ Win,    // [4, H]
             const float* __restrict__ WcH,    // [H, H]
             const float* __restrict__ WcV,    // [H, H]
             const float* __restrict__ bV,     // [H]
             const float* __restrict__ Wout,   // [H, 2]
             const float* __restrict__ bout,   // [2]
             float* __restrict__ out)          // [B]
{
    // Two samples (A, B) per warp/CTA. All arrays per-sample.
    __shared__ __align__(16) float hrowA[L * H], hrowB[L * H];
    __shared__ __align__(16) float vbufA[L * H], vbufB[L * H];
    __shared__ int xrowA[2][L], xrowB[2][L];
    __shared__ __align__(16) float dws[H];

    const int lane = threadIdx.x;
    const int sA = blockIdx.x * 2;

    // ---- per-lane weights (recurrence weights pre-scaled by log2e) ----
    const float win0 = Win[0 * H + lane] * LOG2E;
    const float win1 = Win[1 * H + lane] * LOG2E;
    const float win2 = Win[2 * H + lane] * LOG2E;
    const float win3 = Win[3 * H + lane] * LOG2E;
    const float bv   = bV[lane] * LOG2E;
    const float dbo  = bout[0] - bout[1];
    dws[lane] = Wout[lane * 2 + 0] - Wout[lane * 2 + 1];

    ULL wch[16], wcv[16];
    #pragma unroll
    for (int k = 0; k < 16; k++) {
        wch[k] = pack2(WcH[(2 * k) * H + lane] * LOG2E, WcH[(2 * k + 1) * H + lane] * LOG2E);
        wcv[k] = pack2(WcV[(2 * k) * H + lane] * LOG2E, WcV[(2 * k + 1) * H + lane] * LOG2E);
    }

    const int* xsA = x + (long)sA * (L * L);
    const int* xsB = xsA + (L * L);

    // Row 0: x rows and vbuf preamble (cV = 0, stateV = 0 -> bias + stateH).
    xrowA[0][lane]      = xsA[lane];
    xrowA[0][lane + 32] = xsA[lane + 32];
    xrowB[0][lane]      = xsB[lane];
    xrowB[0][lane + 32] = xsB[lane + 32];
    __syncwarp();
    {
        float waA = 0.f, waB = 0.f;
        #pragma unroll 4
        for (int c = 0; c < L; c++) {
            vbufA[(c << 5) + lane] = bv + waA;
            vbufB[(c << 5) + lane] = bv + waB;
            waA = xrowA[0][c] ? win1 : win0;
            waB = xrowB[0][c] ? win1 : win0;
        }
    }

    ULL hrepA[16], hrepB[16];
    float logA = 0.f, logB = 0.f;
    int c0 = 0, dir = 1;

    for (int r = 0; r < L; r++) {
        const int cur = r & 1, nxt = cur ^ 1;

        // Order prev row's head reads (hrow/xrow) before this row's writes.
        __syncwarp();
        const int rl = (r < L - 1) ? r + 1 : r;
        xrowA[nxt][lane]      = xsA[rl * L + lane];
        xrowA[nxt][lane + 32] = xsA[rl * L + lane + 32];
        xrowB[nxt][lane]      = xsB[rl * L + lane];
        xrowB[nxt][lane + 32] = xsB[rl * L + lane + 32];
        __syncwarp();

        int c = c0;

        // ---- step 0: no horizontal carry ----
        {
            const float hA = elu2(vbufA[(c << 5) + lane]);
            const float hB = elu2(vbufB[(c << 5) + lane]);
            hrowA[(c << 5) + lane] = hA;
            hrowB[(c << 5) + lane] = hB;
            __syncwarp();
            const ulonglong2* pa = reinterpret_cast<const ulonglong2*>(hrowA + (c << 5));
            const ulonglong2* pb = reinterpret_cast<const ulonglong2*>(hrowB + (c << 5));
            #pragma unroll
            for (int k = 0; k < 8; k++) {
                ulonglong2 va = pa[k]; hrepA[2 * k] = va.x; hrepA[2 * k + 1] = va.y;
                ulonglong2 vb = pb[k]; hrepB[2 * k] = vb.x; hrepB[2 * k + 1] = vb.y;
            }
        }
        float vpreA = vbufA[((c + dir) << 5) + lane];
        float vpreB = vbufB[((c + dir) << 5) + lane];
        int xcA = xrowA[cur][c], xnA = xrowA[nxt][c + dir];
        int xcB = xrowB[cur][c], xnB = xrowB[nxt][c + dir];

        // ---- fused loop: with hrep(c) compute pre(c+dir) AND produce(c), x2 ----
        #pragma unroll 2
        for (int j = 0; j < L - 1; j++) {
            const int cn = c + dir;
            const float rsA = bv + (xnA ? win1 : win0) + (xcA ? win3 : win2);
            const float rsB = bv + (xnB ? win1 : win0) + (xcB ? win3 : win2);

            ULL a0 = pack2(vpreA, 0.f), a1 = 0ull;
            ULL b0 = pack2(vpreB, 0.f), b1 = 0ull;
            ULL u0 = pack2(rsA, 0.f),   u1 = 0ull;
            ULL w0 = pack2(rsB, 0.f),   w1 = 0ull;
            #pragma unroll
            for (int k = 0; k < 16; k += 2) {
                a0 = ffma2(hrepA[k + 0], wch[k + 0], a0);
                b0 = ffma2(hrepB[k + 0], wch[k + 0], b0);
                a1 = ffma2(hrepA[k + 1], wch[k + 1], a1);
                b1 = ffma2(hrepB[k + 1], wch[k + 1], b1);
            }
            #pragma unroll
            for (int k = 0; k < 16; k += 2) {
                u0 = ffma2(hrepA[k + 0], wcv[k + 0], u0);
                w0 = ffma2(hrepB[k + 0], wcv[k + 0], w0);
                u1 = ffma2(hrepA[k + 1], wcv[k + 1], u1);
                w1 = ffma2(hrepB[k + 1], wcv[k + 1], w1);
            }
            float lo, hi;
            a0 = fadd2(a0, a1); unpack2(a0, lo, hi);
            const float hA = elu2(lo + hi);
            b0 = fadd2(b0, b1); unpack2(b0, lo, hi);
            const float hB = elu2(lo + hi);
            hrowA[(cn << 5) + lane] = hA;
            hrowB[(cn << 5) + lane] = hB;
            u0 = fadd2(u0, u1); unpack2(u0, lo, hi);
            vbufA[(c << 5) + lane] = lo + hi;
            w0 = fadd2(w0, w1); unpack2(w0, lo, hi);
            vbufB[(c << 5) + lane] = lo + hi;
            __syncwarp();

            // Broadcast-replicate h(cn); prefetch next-iter operands in the window.
            {
                const ulonglong2* pa = reinterpret_cast<const ulonglong2*>(hrowA + (cn << 5));
                const ulonglong2* pb = reinterpret_cast<const ulonglong2*>(hrowB + (cn << 5));
                #pragma unroll
                for (int k = 0; k < 8; k++) {
                    ulonglong2 va = pa[k]; hrepA[2 * k] = va.x; hrepA[2 * k + 1] = va.y;
                    ulonglong2 vb = pb[k]; hrepB[2 * k] = vb.x; hrepB[2 * k + 1] = vb.y;
                }
            }
            int cn2 = cn + dir;
            cn2 = (cn2 < 0) ? 0 : ((cn2 > L - 1) ? L - 1 : cn2);   // clamp; stale ok
            vpreA = vbufA[(cn2 << 5) + lane];
            vpreB = vbufB[(cn2 << 5) + lane];
            xcA = xrowA[cur][cn]; xnA = xrowA[nxt][cn2];
            xcB = xrowB[cur][cn]; xnB = xrowB[nxt][cn2];
            c = cn;
        }

        // ---- epilogue: produce(c_last) — next row starts here, no stateH ----
        {
            ULL u0 = pack2(bv + (xcA ? win3 : win2), 0.f), u1 = 0ull;
            ULL w0 = pack2(bv + (xcB ? win3 : win2), 0.f), w1 = 0ull;
            #pragma unroll
            for (int k = 0; k < 16; k += 2) {
                u0 = ffma2(hrepA[k + 0], wcv[k + 0], u0);
                w0 = ffma2(hrepB[k + 0], wcv[k + 0], w0);
                u1 = ffma2(hrepA[k + 1], wcv[k + 1], u1);
                w1 = ffma2(hrepB[k + 1], wcv[k + 1], w1);
            }
            float lo, hi;
            u0 = fadd2(u0, u1); unpack2(u0, lo, hi);
            vbufA[(c << 5) + lane] = lo + hi;
            w0 = fadd2(w0, w1); unpack2(w0, lo, hi);
            vbufB[(c << 5) + lane] = lo + hi;
        }

        // ---- row-batched output head: lane handles columns lane, lane+32 ----
        #pragma unroll
        for (int t = 0; t < 2; t++) {
            const int cc = lane + 32 * t;
            const ulonglong2* ha = reinterpret_cast<const ulonglong2*>(hrowA + (cc << 5));
            const ulonglong2* hb = reinterpret_cast<const ulonglong2*>(hrowB + (cc << 5));
            const ulonglong2* dwp = reinterpret_cast<const ulonglong2*>(dws);
            ULL qa0 = 0ull, qa1 = 0ull, qb0 = 0ull, qb1 = 0ull;
            #pragma unroll
            for (int k = 0; k < 8; k++) {
                const int kk = (k + lane) & 7;   // bank-rotate
                ulonglong2 dv = dwp[kk];
                ulonglong2 va = ha[kk];
                ulonglong2 vb = hb[kk];
                qa0 = ffma2(va.x, dv.x, qa0);
                qa1 = ffma2(va.y, dv.y, qa1);
                qb0 = ffma2(vb.x, dv.x, qb0);
                qb1 = ffma2(vb.y, dv.y, qb1);
            }
            float lo, hi;
            qa0 = fadd2(qa0, qa1); unpack2(qa0, lo, hi);
            const float qA = lo + hi + dbo;
            qb0 = fadd2(qb0, qb1); unpack2(qb0, lo, hi);
            const float qB = lo + hi + dbo;
            const float tA = xrowA[cur][cc] ? qA : -qA;
            const float tB = xrowB[cur][cc] ? qB : -qB;
            logA -= fmaxf(tA, 0.f) + __logf(1.f + __expf(-fabsf(tA)));
            logB -= fmaxf(tB, 0.f) + __logf(1.f + __expf(-fabsf(tB)));
        }

        c0 = c;          // snake: next row starts where this one ended
        dir = -dir;
    }

    #pragma unroll
    for (int off = 16; off; off >>= 1) {
        logA += __shfl_xor_sync(FULLMASK, logA, off);
        logB += __shfl_xor_sync(FULLMASK, logB, off);
    }
    if (lane == 0) {
        out[sA]     = 0.5f * logA;
        out[sA + 1] = 0.5f * logB;
    }
}

extern "C" void kernel_launch(void* const* d_in, const int* in_sizes, int n_in,
                              void* d_out, int out_size)
{
    const int*   x    = (const int*)  d_in[0];
    const float* Win  = (const float*)d_in[1];
    const float* WcH  = (const float*)d_in[2];
    const float* WcV  = (const float*)d_in[3];
    const float* bV   = (const float*)d_in[4];
    const float* Wout = (const float*)d_in[5];
    const float* bout = (const float*)d_in[6];
    float* out = (float*)d_out;

    rnn2d_kernel<<<B / 2, 32>>>(x, Win, WcH, WcV, bV, Wout, bout, out);
}